// round 1
// baseline (speedup 1.0000x reference)
#include <cuda_runtime.h>
#include <math.h>

// Problem constants
#define D_    1024
#define S_    1024
#define BB_   2
#define NTOK  2048          // B*S
#define NH_   16
#define DH_   64
#define E_    8
#define KSEL  2
#define FF_   4096
#define NSLOT 4096          // NTOK*KSEL

// ---------------- static scratch (no allocations allowed) ----------------
__device__ float g_xn[NTOK * D_];
__device__ float g_q[NTOK * D_];
__device__ float g_k[NTOK * D_];
__device__ float g_v[NTOK * D_];
__device__ float g_scores[(size_t)BB_ * NH_ * S_ * S_];   // 128 MiB
__device__ float g_attnout[NTOK * D_];
__device__ float g_x2[NTOK * D_];
__device__ float g_h[NTOK * D_];
__device__ float g_act[(size_t)NSLOT * FF_];              // 64 MiB
__device__ float g_y[(size_t)NSLOT * D_];                 // 16 MiB
__device__ float g_topval[NTOK * KSEL];
__device__ int   g_topidx[NTOK * KSEL];
__device__ int   g_slotof[NTOK * KSEL];
__device__ int   g_perm[NSLOT];
__device__ int   g_counts[E_];
__device__ int   g_offs[E_ + 1];
__device__ int   g_cursor[E_];
__device__ float g_probsum[E_];

// ---------------- small utility kernels ----------------
__global__ void init_kernel() {
    int i = threadIdx.x;
    if (i < E_) { g_counts[i] = 0; g_cursor[i] = 0; g_probsum[i] = 0.f; }
}

__global__ void rmsnorm_kernel(const float* __restrict__ X,
                               const float* __restrict__ W,
                               float* __restrict__ O) {
    int t = blockIdx.x;
    const float* x = X + (size_t)t * D_;
    float* o = O + (size_t)t * D_;
    float ss = 0.f;
    for (int d = threadIdx.x; d < D_; d += 256) { float v = x[d]; ss += v * v; }
    __shared__ float red[256];
    red[threadIdx.x] = ss;
    __syncthreads();
    for (int s = 128; s > 0; s >>= 1) {
        if (threadIdx.x < s) red[threadIdx.x] += red[threadIdx.x + s];
        __syncthreads();
    }
    float scale = rsqrtf(red[0] * (1.f / D_) + 1e-6f);
    for (int d = threadIdx.x; d < D_; d += 256) o[d] = x[d] * scale * W[d];
}

// softmax over causal row (scale 1/sqrt(64)=0.125 folded in), zeros above diag
__global__ void softmax_kernel(float* __restrict__ SC) {
    int row = blockIdx.x;                 // 0 .. B*NH*S-1
    int bh = row >> 10, q = row & 1023;
    float* s = SC + (size_t)bh * S_ * S_ + (size_t)q * S_;
    int len = q + 1;
    int tid = threadIdx.x;
    __shared__ float red[128];
    float mx = -1e30f;
    for (int j = tid; j < len; j += 128) mx = fmaxf(mx, s[j]);
    red[tid] = mx; __syncthreads();
    for (int st = 64; st > 0; st >>= 1) {
        if (tid < st) red[tid] = fmaxf(red[tid], red[tid + st]);
        __syncthreads();
    }
    mx = red[0] * 0.125f;
    __syncthreads();
    float sum = 0.f;
    for (int j = tid; j < len; j += 128) {
        float p = expf(s[j] * 0.125f - mx);
        s[j] = p;
        sum += p;
    }
    red[tid] = sum; __syncthreads();
    for (int st = 64; st > 0; st >>= 1) {
        if (tid < st) red[tid] += red[tid + st];
        __syncthreads();
    }
    float inv = 1.f / red[0];
    for (int j = tid; j < len; j += 128) s[j] *= inv;
    for (int j = len + tid; j < S_; j += 128) s[j] = 0.f;
}

__global__ void router_kernel(const float* __restrict__ H,
                              const float* __restrict__ RW) {
    int t = blockIdx.x;
    int tid = threadIdx.x;
    int e = tid >> 5, lane = tid & 31;
    const float* h = H + (size_t)t * D_;
    float p = 0.f;
    for (int d = lane; d < D_; d += 32) p += h[d] * RW[d * E_ + e];
    for (int o = 16; o > 0; o >>= 1) p += __shfl_down_sync(0xffffffff, p, o);
    __shared__ float lg[E_];
    if (lane == 0) lg[e] = p;
    __syncthreads();
    if (tid == 0) {
        float mx = lg[0];
        for (int i = 1; i < E_; i++) mx = fmaxf(mx, lg[i]);
        float pr[E_]; float s = 0.f;
        for (int i = 0; i < E_; i++) { pr[i] = expf(lg[i] - mx); s += pr[i]; }
        float inv = 1.f / s;
        float b1v = -1.f, b2v = -1.f; int b1i = 0, b2i = 0;
        for (int i = 0; i < E_; i++) {
            float v = pr[i] * inv;
            atomicAdd(&g_probsum[i], v);
            if (v > b1v) { b2v = b1v; b2i = b1i; b1v = v; b1i = i; }
            else if (v > b2v) { b2v = v; b2i = i; }
        }
        g_topidx[t * 2] = b1i; g_topidx[t * 2 + 1] = b2i;
        g_topval[t * 2] = b1v; g_topval[t * 2 + 1] = b2v;
        atomicAdd(&g_counts[b1i], 1);
        atomicAdd(&g_counts[b2i], 1);
    }
}

__global__ void scan_kernel() {
    if (threadIdx.x == 0) {
        g_offs[0] = 0;
        for (int e = 0; e < E_; e++) {
            g_offs[e + 1] = g_offs[e] + g_counts[e];
            g_cursor[e] = g_offs[e];
        }
    }
}

__global__ void place_kernel() {
    int t = blockIdx.x * blockDim.x + threadIdx.x;
    if (t >= NTOK) return;
    for (int kk = 0; kk < KSEL; kk++) {
        int e = g_topidx[t * 2 + kk];
        int slot = atomicAdd(&g_cursor[e], 1);
        g_perm[slot] = t;
        g_slotof[t * 2 + kk] = slot;
    }
}

__global__ void combine_kernel(float* __restrict__ out) {
    int idx = blockIdx.x * blockDim.x + threadIdx.x;
    if (idx >= NTOK * D_) return;
    int t = idx >> 10, d = idx & 1023;
    float v = g_x2[idx];
    v += g_topval[t * 2]     * g_y[(size_t)g_slotof[t * 2]     * D_ + d];
    v += g_topval[t * 2 + 1] * g_y[(size_t)g_slotof[t * 2 + 1] * D_ + d];
    out[idx] = v;
}

__global__ void finalize_kernel(float* __restrict__ out) {
    if (threadIdx.x == 0) {
        float loss = 0.f;
        for (int e = 0; e < E_; e++)
            loss += ((float)g_counts[e] / (float)NSLOT) * (g_probsum[e] / (float)NTOK);
        loss *= (float)E_;
        out[(size_t)NTOK * D_] = loss;
        for (int e = 0; e < E_; e++)
            out[(size_t)NTOK * D_ + 1 + e] = (float)g_counts[e];
    }
}

// ---------------- batched SGEMM 128x128x8, 8x8 microtile ----------------
// TB: B matrix stored [N,K] (computes A * B^T). EPI: 0 none, 1 add residual.
// mode: 0 none, 1 causal tile-skip (C[m,n] only needed for n<=m),
//       2 k-clip (A columns >= m0+128 known zero).
template <bool TB, int EPI>
__global__ void sgemm(const float* __restrict__ A, int lda,
                      const float* __restrict__ Bmat, int ldb,
                      float* __restrict__ C, int ldc,
                      int M, int N, int K,
                      long long aO, long long aI, long long bO, long long bI,
                      long long cO, long long cI, int zdiv,
                      const float* __restrict__ addp, int mode) {
    int z = blockIdx.z;
    int zo = z / zdiv, zi = z % zdiv;
    A += zo * aO + zi * aI;
    Bmat += zo * bO + zi * bI;
    C += zo * cO + zi * cI;

    int m0 = blockIdx.y * 128, n0 = blockIdx.x * 128;
    if (mode == 1 && n0 > m0 + 127) return;
    int Keff = (mode == 2) ? min(K, m0 + 128) : K;

    __shared__ float As[8][132];
    __shared__ float Bs[8][132];

    int tid = threadIdx.x;
    int ar = tid >> 1;             // 0..127
    int akv = (tid & 1) * 4;       // 0 or 4
    int brow = tid >> 5;           // 0..7
    int bcol = (tid & 31) * 4;     // 0..124
    int tr = tid >> 4, tc = tid & 15;

    float acc[8][8];
#pragma unroll
    for (int i = 0; i < 8; i++)
#pragma unroll
        for (int j = 0; j < 8; j++) acc[i][j] = 0.f;

    for (int k0 = 0; k0 < Keff; k0 += 8) {
        float4 av = make_float4(0.f, 0.f, 0.f, 0.f);
        int gar = m0 + ar;
        if (gar < M) av = *(const float4*)(A + (size_t)gar * lda + k0 + akv);
        As[akv + 0][ar] = av.x; As[akv + 1][ar] = av.y;
        As[akv + 2][ar] = av.z; As[akv + 3][ar] = av.w;
        if (TB) {
            float4 bv = make_float4(0.f, 0.f, 0.f, 0.f);
            int gn = n0 + ar;
            if (gn < N) bv = *(const float4*)(Bmat + (size_t)gn * ldb + k0 + akv);
            Bs[akv + 0][ar] = bv.x; Bs[akv + 1][ar] = bv.y;
            Bs[akv + 2][ar] = bv.z; Bs[akv + 3][ar] = bv.w;
        } else {
            float4 bv = make_float4(0.f, 0.f, 0.f, 0.f);
            int gn = n0 + bcol;
            if (gn < N) bv = *(const float4*)(Bmat + (size_t)(k0 + brow) * ldb + gn);
            *(float4*)&Bs[brow][bcol] = bv;
        }
        __syncthreads();
#pragma unroll
        for (int kk = 0; kk < 8; kk++) {
            float a[8], b[8];
#pragma unroll
            for (int i = 0; i < 8; i++) a[i] = As[kk][tr * 8 + i];
#pragma unroll
            for (int j = 0; j < 8; j++) b[j] = Bs[kk][tc * 8 + j];
#pragma unroll
            for (int i = 0; i < 8; i++)
#pragma unroll
                for (int j = 0; j < 8; j++) acc[i][j] += a[i] * b[j];
        }
        __syncthreads();
    }

#pragma unroll
    for (int i = 0; i < 8; i++) {
        int r = m0 + tr * 8 + i;
        if (r < M) {
#pragma unroll
            for (int j = 0; j < 8; j++) {
                int c = n0 + tc * 8 + j;
                if (c < N) {
                    float v = acc[i][j];
                    if (EPI == 1) v += addp[(size_t)r * ldc + c];
                    C[(size_t)r * ldc + c] = v;
                }
            }
        }
    }
}

// ---------------- grouped MoE GEMMs ----------------
__device__ __forceinline__ float gelu_tanh(float v) {
    float v3 = v * v * v;
    return 0.5f * v * (1.f + tanhf(0.7978845608028654f * (v + 0.044715f * v3)));
}

// ACT[slot, :] = gelu(H[perm[slot], :] @ W1[e] + b1[e])   (N=FF_, K=D_)
__global__ void moe_gemm1(const float* __restrict__ H,
                          const float* __restrict__ W1,
                          const float* __restrict__ B1) {
    int e = blockIdx.z;
    int base = g_offs[e], cnt = g_offs[e + 1] - base;
    int m0 = blockIdx.y * 128;
    if (m0 >= cnt) return;
    int n0 = blockIdx.x * 128;
    const float* Bmat = W1 + (size_t)e * D_ * FF_;

    __shared__ float As[8][132];
    __shared__ float Bs[8][132];
    int tid = threadIdx.x;
    int ar = tid >> 1, akv = (tid & 1) * 4;
    int brow = tid >> 5, bcol = (tid & 31) * 4;
    int tr = tid >> 4, tc = tid & 15;

    const float* aptr = nullptr;
    if (m0 + ar < cnt) aptr = H + (size_t)g_perm[base + m0 + ar] * D_;

    float acc[8][8];
#pragma unroll
    for (int i = 0; i < 8; i++)
#pragma unroll
        for (int j = 0; j < 8; j++) acc[i][j] = 0.f;

    for (int k0 = 0; k0 < D_; k0 += 8) {
        float4 av = aptr ? *(const float4*)(aptr + k0 + akv)
                         : make_float4(0.f, 0.f, 0.f, 0.f);
        As[akv + 0][ar] = av.x; As[akv + 1][ar] = av.y;
        As[akv + 2][ar] = av.z; As[akv + 3][ar] = av.w;
        float4 bv = *(const float4*)(Bmat + (size_t)(k0 + brow) * FF_ + n0 + bcol);
        *(float4*)&Bs[brow][bcol] = bv;
        __syncthreads();
#pragma unroll
        for (int kk = 0; kk < 8; kk++) {
            float a[8], b[8];
#pragma unroll
            for (int i = 0; i < 8; i++) a[i] = As[kk][tr * 8 + i];
#pragma unroll
            for (int j = 0; j < 8; j++) b[j] = Bs[kk][tc * 8 + j];
#pragma unroll
            for (int i = 0; i < 8; i++)
#pragma unroll
                for (int j = 0; j < 8; j++) acc[i][j] += a[i] * b[j];
        }
        __syncthreads();
    }

#pragma unroll
    for (int i = 0; i < 8; i++) {
        int r = m0 + tr * 8 + i;
        if (r < cnt) {
            size_t orow = (size_t)(base + r) * FF_;
#pragma unroll
            for (int j = 0; j < 8; j++) {
                int c = n0 + tc * 8 + j;
                float v = acc[i][j] + B1[e * FF_ + c];
                g_act[orow + c] = gelu_tanh(v);
            }
        }
    }
}

// Y[slot, :] = ACT[slot, :] @ W2[e] + b2[e]   (N=D_, K=FF_)
__global__ void moe_gemm2(const float* __restrict__ W2,
                          const float* __restrict__ B2) {
    int e = blockIdx.z;
    int base = g_offs[e], cnt = g_offs[e + 1] - base;
    int m0 = blockIdx.y * 128;
    if (m0 >= cnt) return;
    int n0 = blockIdx.x * 128;
    const float* Bmat = W2 + (size_t)e * FF_ * D_;

    __shared__ float As[8][132];
    __shared__ float Bs[8][132];
    int tid = threadIdx.x;
    int ar = tid >> 1, akv = (tid & 1) * 4;
    int brow = tid >> 5, bcol = (tid & 31) * 4;
    int tr = tid >> 4, tc = tid & 15;

    const float* aptr = nullptr;
    if (m0 + ar < cnt) aptr = g_act + (size_t)(base + m0 + ar) * FF_;

    float acc[8][8];
#pragma unroll
    for (int i = 0; i < 8; i++)
#pragma unroll
        for (int j = 0; j < 8; j++) acc[i][j] = 0.f;

    for (int k0 = 0; k0 < FF_; k0 += 8) {
        float4 av = aptr ? *(const float4*)(aptr + k0 + akv)
                         : make_float4(0.f, 0.f, 0.f, 0.f);
        As[akv + 0][ar] = av.x; As[akv + 1][ar] = av.y;
        As[akv + 2][ar] = av.z; As[akv + 3][ar] = av.w;
        float4 bv = *(const float4*)(Bmat + (size_t)(k0 + brow) * D_ + n0 + bcol);
        *(float4*)&Bs[brow][bcol] = bv;
        __syncthreads();
#pragma unroll
        for (int kk = 0; kk < 8; kk++) {
            float a[8], b[8];
#pragma unroll
            for (int i = 0; i < 8; i++) a[i] = As[kk][tr * 8 + i];
#pragma unroll
            for (int j = 0; j < 8; j++) b[j] = Bs[kk][tc * 8 + j];
#pragma unroll
            for (int i = 0; i < 8; i++)
#pragma unroll
                for (int j = 0; j < 8; j++) acc[i][j] += a[i] * b[j];
        }
        __syncthreads();
    }

#pragma unroll
    for (int i = 0; i < 8; i++) {
        int r = m0 + tr * 8 + i;
        if (r < cnt) {
            size_t orow = (size_t)(base + r) * D_;
#pragma unroll
            for (int j = 0; j < 8; j++) {
                int c = n0 + tc * 8 + j;
                g_y[orow + c] = acc[i][j] + B2[e * D_ + c];
            }
        }
    }
}

// ---------------- launch ----------------
extern "C" void kernel_launch(void* const* d_in, const int* in_sizes, int n_in,
                              void* d_out, int out_size) {
    const float* x     = (const float*)d_in[0];
    const float* anw   = (const float*)d_in[1];
    const float* wq    = (const float*)d_in[2];
    const float* wk    = (const float*)d_in[3];
    const float* wv    = (const float*)d_in[4];
    const float* wo    = (const float*)d_in[5];
    const float* mnw   = (const float*)d_in[6];
    const float* rw    = (const float*)d_in[7];
    const float* w1    = (const float*)d_in[8];
    const float* b1    = (const float*)d_in[9];
    const float* w2    = (const float*)d_in[10];
    const float* b2    = (const float*)d_in[11];
    float* out = (float*)d_out;

    float *xn, *q, *k, *v, *sc, *ao, *x2, *h;
    cudaGetSymbolAddress((void**)&xn, g_xn);
    cudaGetSymbolAddress((void**)&q,  g_q);
    cudaGetSymbolAddress((void**)&k,  g_k);
    cudaGetSymbolAddress((void**)&v,  g_v);
    cudaGetSymbolAddress((void**)&sc, g_scores);
    cudaGetSymbolAddress((void**)&ao, g_attnout);
    cudaGetSymbolAddress((void**)&x2, g_x2);
    cudaGetSymbolAddress((void**)&h,  g_h);

    init_kernel<<<1, 32>>>();

    // 1) rmsnorm(x) -> xn
    rmsnorm_kernel<<<NTOK, 256>>>(x, anw, xn);

    // 2) Q,K,V projections: [2048x1024] @ [1024x1024]
    dim3 gproj(8, 16, 1);
    sgemm<false, 0><<<gproj, 256>>>(xn, D_, wq, D_, q, D_, NTOK, D_, D_,
                                    0, 0, 0, 0, 0, 0, 1, nullptr, 0);
    sgemm<false, 0><<<gproj, 256>>>(xn, D_, wk, D_, k, D_, NTOK, D_, D_,
                                    0, 0, 0, 0, 0, 0, 1, nullptr, 0);
    sgemm<false, 0><<<gproj, 256>>>(xn, D_, wv, D_, v, D_, NTOK, D_, D_,
                                    0, 0, 0, 0, 0, 0, 1, nullptr, 0);

    // 3) scores[bh] = Q[b,:,h*64:] @ K[b,:,h*64:]^T  (causal tile skip)
    {
        dim3 g(8, 8, BB_ * NH_);
        long long sSD = (long long)S_ * D_;
        long long sSS = (long long)S_ * S_;
        sgemm<true, 0><<<g, 256>>>(q, D_, k, D_, sc, S_, S_, S_, DH_,
                                   sSD, DH_, sSD, DH_, NH_ * sSS, sSS, NH_,
                                   nullptr, 1);
    }

    // 4) softmax rows (causal)
    softmax_kernel<<<BB_ * NH_ * S_, 128>>>(sc);

    // 5) attnout[b,:,h*64:] = P[bh] @ V[b,:,h*64:]  (k-clipped)
    {
        dim3 g(1, 8, BB_ * NH_);
        long long sSD = (long long)S_ * D_;
        long long sSS = (long long)S_ * S_;
        sgemm<false, 0><<<g, 256>>>(sc, S_, v, D_, ao, D_, S_, DH_, S_,
                                    NH_ * sSS, sSS, sSD, DH_, sSD, DH_, NH_,
                                    nullptr, 2);
    }

    // 6) x2 = x + attnout @ wo
    sgemm<false, 1><<<gproj, 256>>>(ao, D_, wo, D_, x2, D_, NTOK, D_, D_,
                                    0, 0, 0, 0, 0, 0, 1, x, 0);

    // 7) rmsnorm(x2) -> h
    rmsnorm_kernel<<<NTOK, 256>>>(x2, mnw, h);

    // 8) router: probs, top-2, counts, probsum
    router_kernel<<<NTOK, 256>>>(h, rw);
    scan_kernel<<<1, 1>>>();
    place_kernel<<<(NTOK + 255) / 256, 256>>>();

    // 9) expert GEMMs (grouped, early-exit on count)
    moe_gemm1<<<dim3(FF_ / 128, NSLOT / 128, E_), 256>>>(h, w1, b1);
    moe_gemm2<<<dim3(D_ / 128, NSLOT / 128, E_), 256>>>(w2, b2);

    // 10) out = residual + gated combine; then loss + counts
    combine_kernel<<<(NTOK * D_ + 255) / 256, 256>>>(out);
    finalize_kernel<<<1, 32>>>(out);
}

// round 2
// speedup vs baseline: 2.9567x; 2.9567x over previous
#include <cuda_runtime.h>
#include <math.h>

// Problem constants
#define D_    1024
#define S_    1024
#define BB_   2
#define NTOK  2048          // B*S
#define NH_   16
#define DH_   64
#define E_    8
#define KSEL  2
#define FF_   4096
#define NSLOT 4096          // NTOK*KSEL

#define BM 128
#define BN 128
#define BK 32
#define ASTRIDE 36          // BK+4: frag loads 4g+t -> conflict-free
#define BSTRIDE 136         // BN+8: frag loads 8t+g -> conflict-free

// ---------------- static scratch ----------------
__device__ float g_xn[NTOK * D_];
__device__ float g_q[NTOK * D_];
__device__ float g_k[NTOK * D_];
__device__ float g_v[NTOK * D_];
__device__ float g_scores[(size_t)BB_ * NH_ * S_ * S_];
__device__ float g_attnout[NTOK * D_];
__device__ float g_x2[NTOK * D_];
__device__ float g_h[NTOK * D_];
__device__ float g_act[(size_t)NSLOT * FF_];
__device__ float g_y[(size_t)NSLOT * D_];
__device__ float g_topval[NTOK * KSEL];
__device__ int   g_topidx[NTOK * KSEL];
__device__ int   g_slotof[NTOK * KSEL];
__device__ int   g_perm[NSLOT];
__device__ int   g_counts[E_];
__device__ int   g_offs[E_ + 1];
__device__ int   g_cursor[E_];
__device__ float g_probsum[E_];

// ---------------- helpers ----------------
__device__ __forceinline__ unsigned f2tf(float f) {
    unsigned u; asm("cvt.rna.tf32.f32 %0, %1;" : "=r"(u) : "f"(f)); return u;
}
__device__ __forceinline__ void mma_tf32(float* d, const unsigned* a, const unsigned* b) {
    asm volatile(
        "mma.sync.aligned.m16n8k8.row.col.f32.tf32.tf32.f32 "
        "{%0,%1,%2,%3}, {%4,%5,%6,%7}, {%8,%9}, {%0,%1,%2,%3};"
        : "+f"(d[0]), "+f"(d[1]), "+f"(d[2]), "+f"(d[3])
        : "r"(a[0]), "r"(a[1]), "r"(a[2]), "r"(a[3]), "r"(b[0]), "r"(b[1]));
}
__device__ __forceinline__ float gelu_tanh(float v) {
    float v3 = v * v * v;
    return 0.5f * v * (1.f + tanhf(0.7978845608028654f * (v + 0.044715f * v3)));
}

// ---------------- small utility kernels ----------------
__global__ void init_kernel() {
    int i = threadIdx.x;
    if (i < E_) { g_counts[i] = 0; g_cursor[i] = 0; g_probsum[i] = 0.f; }
}

__global__ void rmsnorm_kernel(const float* __restrict__ X,
                               const float* __restrict__ W,
                               float* __restrict__ O) {
    int t = blockIdx.x;
    const float* x = X + (size_t)t * D_;
    float* o = O + (size_t)t * D_;
    float ss = 0.f;
    for (int d = threadIdx.x; d < D_; d += 256) { float v = x[d]; ss += v * v; }
    __shared__ float red[256];
    red[threadIdx.x] = ss;
    __syncthreads();
    for (int s = 128; s > 0; s >>= 1) {
        if (threadIdx.x < s) red[threadIdx.x] += red[threadIdx.x + s];
        __syncthreads();
    }
    float scale = rsqrtf(red[0] * (1.f / D_) + 1e-6f);
    for (int d = threadIdx.x; d < D_; d += 256) o[d] = x[d] * scale * W[d];
}

__global__ void softmax_kernel(float* __restrict__ SC) {
    int row = blockIdx.x;
    int bh = row >> 10, q = row & 1023;
    float* s = SC + (size_t)bh * S_ * S_ + (size_t)q * S_;
    int len = q + 1;
    int tid = threadIdx.x;
    __shared__ float red[128];
    float mx = -1e30f;
    for (int j = tid; j < len; j += 128) mx = fmaxf(mx, s[j]);
    red[tid] = mx; __syncthreads();
    for (int st = 64; st > 0; st >>= 1) {
        if (tid < st) red[tid] = fmaxf(red[tid], red[tid + st]);
        __syncthreads();
    }
    mx = red[0] * 0.125f;
    __syncthreads();
    float sum = 0.f;
    for (int j = tid; j < len; j += 128) {
        float p = expf(s[j] * 0.125f - mx);
        s[j] = p;
        sum += p;
    }
    red[tid] = sum; __syncthreads();
    for (int st = 64; st > 0; st >>= 1) {
        if (tid < st) red[tid] += red[tid + st];
        __syncthreads();
    }
    float inv = 1.f / red[0];
    for (int j = tid; j < len; j += 128) s[j] *= inv;
    for (int j = len + tid; j < S_; j += 128) s[j] = 0.f;
}

__global__ void router_kernel(const float* __restrict__ H,
                              const float* __restrict__ RW) {
    int t = blockIdx.x;
    int tid = threadIdx.x;
    int e = tid >> 5, lane = tid & 31;
    const float* h = H + (size_t)t * D_;
    float p = 0.f;
    for (int d = lane; d < D_; d += 32) p += h[d] * RW[d * E_ + e];
    for (int o = 16; o > 0; o >>= 1) p += __shfl_down_sync(0xffffffff, p, o);
    __shared__ float lg[E_];
    if (lane == 0) lg[e] = p;
    __syncthreads();
    if (tid == 0) {
        float mx = lg[0];
        for (int i = 1; i < E_; i++) mx = fmaxf(mx, lg[i]);
        float pr[E_]; float s = 0.f;
        for (int i = 0; i < E_; i++) { pr[i] = expf(lg[i] - mx); s += pr[i]; }
        float inv = 1.f / s;
        float b1v = -1.f, b2v = -1.f; int b1i = 0, b2i = 0;
        for (int i = 0; i < E_; i++) {
            float v = pr[i] * inv;
            atomicAdd(&g_probsum[i], v);
            if (v > b1v) { b2v = b1v; b2i = b1i; b1v = v; b1i = i; }
            else if (v > b2v) { b2v = v; b2i = i; }
        }
        g_topidx[t * 2] = b1i; g_topidx[t * 2 + 1] = b2i;
        g_topval[t * 2] = b1v; g_topval[t * 2 + 1] = b2v;
        atomicAdd(&g_counts[b1i], 1);
        atomicAdd(&g_counts[b2i], 1);
    }
}

__global__ void scan_kernel() {
    if (threadIdx.x == 0) {
        g_offs[0] = 0;
        for (int e = 0; e < E_; e++) {
            g_offs[e + 1] = g_offs[e] + g_counts[e];
            g_cursor[e] = g_offs[e];
        }
    }
}

__global__ void place_kernel() {
    int t = blockIdx.x * blockDim.x + threadIdx.x;
    if (t >= NTOK) return;
    for (int kk = 0; kk < KSEL; kk++) {
        int e = g_topidx[t * 2 + kk];
        int slot = atomicAdd(&g_cursor[e], 1);
        g_perm[slot] = t;
        g_slotof[t * 2 + kk] = slot;
    }
}

__global__ void combine_kernel(float* __restrict__ out) {
    int idx = blockIdx.x * blockDim.x + threadIdx.x;
    if (idx >= NTOK * D_) return;
    int t = idx >> 10, d = idx & 1023;
    float v = g_x2[idx];
    v += g_topval[t * 2]     * g_y[(size_t)g_slotof[t * 2]     * D_ + d];
    v += g_topval[t * 2 + 1] * g_y[(size_t)g_slotof[t * 2 + 1] * D_ + d];
    out[idx] = v;
}

__global__ void finalize_kernel(float* __restrict__ out) {
    if (threadIdx.x == 0) {
        float loss = 0.f;
        for (int e = 0; e < E_; e++)
            loss += ((float)g_counts[e] / (float)NSLOT) * (g_probsum[e] / (float)NTOK);
        loss *= (float)E_;
        out[(size_t)NTOK * D_] = loss;
        for (int e = 0; e < E_; e++)
            out[(size_t)NTOK * D_ + 1 + e] = (float)g_counts[e];
    }
}

// ---------------- tf32 MMA GEMM: 128x128x32 tiles, 8 warps (4m x 2n) -----
// TB: B stored [N,K] (computes A*B^T). EPI: 0 none, 1 add residual addp.
// mode: 0 none, 1 causal tile-skip, 2 k-clip (Keff=min(K,m0+128)).
template <bool TB, int EPI>
__global__ void __launch_bounds__(256, 1)
mgemm(const float* __restrict__ A, int lda,
      const float* __restrict__ Bmat, int ldb,
      float* __restrict__ C, int ldc,
      int M, int N, int K,
      long long aO, long long aI, long long bO, long long bI,
      long long cO, long long cI, int zdiv,
      const float* __restrict__ addp, int mode) {
    int z = blockIdx.z;
    int zo = z / zdiv, zi = z % zdiv;
    A += zo * aO + zi * aI;
    Bmat += zo * bO + zi * bI;
    C += zo * cO + zi * cI;

    int m0 = blockIdx.y * BM, n0 = blockIdx.x * BN;
    if (mode == 1 && n0 > m0 + (BM - 1)) return;
    int Keff = (mode == 2) ? min(K, m0 + BM) : K;

    __shared__ float As[BM][ASTRIDE];
    __shared__ float Bs[BK][BSTRIDE];

    int tid = threadIdx.x;
    int wid = tid >> 5, lane = tid & 31;
    int warpM = wid & 3, warpN = wid >> 2;
    int g = lane >> 2, t = lane & 3;

    float acc[2][8][4];
#pragma unroll
    for (int mt = 0; mt < 2; mt++)
#pragma unroll
        for (int nt = 0; nt < 8; nt++)
#pragma unroll
            for (int r = 0; r < 4; r++) acc[mt][nt][r] = 0.f;

    float4 pa[4], pb[4];
    // prefetch first tile
#pragma unroll
    for (int i = 0; i < 4; i++) {
        int idx = i * 256 + tid;
        int r = idx >> 3, c = (idx & 7) * 4;
        pa[i] = (m0 + r < M) ? *(const float4*)(A + (size_t)(m0 + r) * lda + c)
                             : make_float4(0.f, 0.f, 0.f, 0.f);
        if (TB) {
            pb[i] = (n0 + r < N) ? *(const float4*)(Bmat + (size_t)(n0 + r) * ldb + c)
                                 : make_float4(0.f, 0.f, 0.f, 0.f);
        } else {
            int rb = idx >> 5, cb = (idx & 31) * 4;
            pb[i] = (n0 + cb < N) ? *(const float4*)(Bmat + (size_t)rb * ldb + n0 + cb)
                                  : make_float4(0.f, 0.f, 0.f, 0.f);
        }
    }

    for (int k0 = 0; k0 < Keff; k0 += BK) {
        // regs -> smem (tf32 convert)
#pragma unroll
        for (int i = 0; i < 4; i++) {
            int idx = i * 256 + tid;
            int r = idx >> 3, c = (idx & 7) * 4;
            As[r][c + 0] = __uint_as_float(f2tf(pa[i].x));
            As[r][c + 1] = __uint_as_float(f2tf(pa[i].y));
            As[r][c + 2] = __uint_as_float(f2tf(pa[i].z));
            As[r][c + 3] = __uint_as_float(f2tf(pa[i].w));
            if (TB) {
                Bs[c + 0][r] = __uint_as_float(f2tf(pb[i].x));
                Bs[c + 1][r] = __uint_as_float(f2tf(pb[i].y));
                Bs[c + 2][r] = __uint_as_float(f2tf(pb[i].z));
                Bs[c + 3][r] = __uint_as_float(f2tf(pb[i].w));
            } else {
                int rb = idx >> 5, cb = (idx & 31) * 4;
                Bs[rb][cb + 0] = __uint_as_float(f2tf(pb[i].x));
                Bs[rb][cb + 1] = __uint_as_float(f2tf(pb[i].y));
                Bs[rb][cb + 2] = __uint_as_float(f2tf(pb[i].z));
                Bs[rb][cb + 3] = __uint_as_float(f2tf(pb[i].w));
            }
        }
        __syncthreads();

        // prefetch next tile
        int kn = k0 + BK;
        if (kn < Keff) {
#pragma unroll
            for (int i = 0; i < 4; i++) {
                int idx = i * 256 + tid;
                int r = idx >> 3, c = (idx & 7) * 4;
                pa[i] = (m0 + r < M) ? *(const float4*)(A + (size_t)(m0 + r) * lda + kn + c)
                                     : make_float4(0.f, 0.f, 0.f, 0.f);
                if (TB) {
                    pb[i] = (n0 + r < N) ? *(const float4*)(Bmat + (size_t)(n0 + r) * ldb + kn + c)
                                         : make_float4(0.f, 0.f, 0.f, 0.f);
                } else {
                    int rb = idx >> 5, cb = (idx & 31) * 4;
                    pb[i] = (n0 + cb < N) ? *(const float4*)(Bmat + (size_t)(kn + rb) * ldb + n0 + cb)
                                          : make_float4(0.f, 0.f, 0.f, 0.f);
                }
            }
        }

        // compute
#pragma unroll
        for (int ks = 0; ks < 4; ks++) {
            int kk = ks * 8;
            unsigned afr[2][4];
#pragma unroll
            for (int mt = 0; mt < 2; mt++) {
                int am = warpM * 32 + mt * 16;
                afr[mt][0] = __float_as_uint(As[am + g][kk + t]);
                afr[mt][1] = __float_as_uint(As[am + g + 8][kk + t]);
                afr[mt][2] = __float_as_uint(As[am + g][kk + t + 4]);
                afr[mt][3] = __float_as_uint(As[am + g + 8][kk + t + 4]);
            }
            unsigned bfr[8][2];
#pragma unroll
            for (int nt = 0; nt < 8; nt++) {
                int bn = warpN * 64 + nt * 8;
                bfr[nt][0] = __float_as_uint(Bs[kk + t][bn + g]);
                bfr[nt][1] = __float_as_uint(Bs[kk + t + 4][bn + g]);
            }
#pragma unroll
            for (int mt = 0; mt < 2; mt++)
#pragma unroll
                for (int nt = 0; nt < 8; nt++)
                    mma_tf32(acc[mt][nt], afr[mt], bfr[nt]);
        }
        __syncthreads();
    }

    // epilogue
#pragma unroll
    for (int mt = 0; mt < 2; mt++) {
#pragma unroll
        for (int nt = 0; nt < 8; nt++) {
            int row = m0 + warpM * 32 + mt * 16 + g;
            int col = n0 + warpN * 64 + nt * 8 + 2 * t;
#pragma unroll
            for (int half = 0; half < 2; half++) {
                int r = row + half * 8;
                if (r < M && col < N) {
                    float v0 = acc[mt][nt][half * 2 + 0];
                    float v1 = acc[mt][nt][half * 2 + 1];
                    if (EPI == 1) {
                        float2 ad = *(const float2*)(addp + (size_t)r * ldc + col);
                        v0 += ad.x; v1 += ad.y;
                    }
                    float2 o; o.x = v0; o.y = v1;
                    *(float2*)(C + (size_t)r * ldc + col) = o;
                }
            }
        }
    }
}

// ---------------- grouped MoE GEMMs (tf32 MMA) ----------------
// EP: 1 -> gelu(acc + b1) into g_act (K=D_, N=FF_, A gathered via perm)
// EP: 2 -> acc + b2 into g_y     (K=FF_, N=D_, A = g_act rows)
template <int EP>
__global__ void __launch_bounds__(256, 1)
moe_mgemm(const float* __restrict__ H,
          const float* __restrict__ W,
          const float* __restrict__ Bias,
          int Kdim, int Ndim) {
    int e = blockIdx.z;
    int base = g_offs[e], cnt = g_offs[e + 1] - base;
    int m0 = blockIdx.y * BM;
    if (m0 >= cnt) return;
    int n0 = blockIdx.x * BN;
    const float* Bmat = W + (size_t)e * Kdim * Ndim;

    __shared__ float As[BM][ASTRIDE];
    __shared__ float Bs[BK][BSTRIDE];

    int tid = threadIdx.x;
    int wid = tid >> 5, lane = tid & 31;
    int warpM = wid & 3, warpN = wid >> 2;
    int g = lane >> 2, t = lane & 3;

    // per-thread source row pointers (fixed across k)
    const float* arow[4];
#pragma unroll
    for (int i = 0; i < 4; i++) {
        int idx = i * 256 + tid;
        int r = idx >> 3;
        if (m0 + r < cnt) {
            if (EP == 1) arow[i] = H + (size_t)g_perm[base + m0 + r] * Kdim;
            else         arow[i] = g_act + (size_t)(base + m0 + r) * Kdim;
        } else arow[i] = nullptr;
    }

    float acc[2][8][4];
#pragma unroll
    for (int mt = 0; mt < 2; mt++)
#pragma unroll
        for (int nt = 0; nt < 8; nt++)
#pragma unroll
            for (int r = 0; r < 4; r++) acc[mt][nt][r] = 0.f;

    float4 pa[4], pb[4];
#pragma unroll
    for (int i = 0; i < 4; i++) {
        int idx = i * 256 + tid;
        int c = (idx & 7) * 4;
        pa[i] = arow[i] ? *(const float4*)(arow[i] + c) : make_float4(0.f, 0.f, 0.f, 0.f);
        int rb = idx >> 5, cb = (idx & 31) * 4;
        pb[i] = *(const float4*)(Bmat + (size_t)rb * Ndim + n0 + cb);
    }

    for (int k0 = 0; k0 < Kdim; k0 += BK) {
#pragma unroll
        for (int i = 0; i < 4; i++) {
            int idx = i * 256 + tid;
            int r = idx >> 3, c = (idx & 7) * 4;
            As[r][c + 0] = __uint_as_float(f2tf(pa[i].x));
            As[r][c + 1] = __uint_as_float(f2tf(pa[i].y));
            As[r][c + 2] = __uint_as_float(f2tf(pa[i].z));
            As[r][c + 3] = __uint_as_float(f2tf(pa[i].w));
            int rb = idx >> 5, cb = (idx & 31) * 4;
            Bs[rb][cb + 0] = __uint_as_float(f2tf(pb[i].x));
            Bs[rb][cb + 1] = __uint_as_float(f2tf(pb[i].y));
            Bs[rb][cb + 2] = __uint_as_float(f2tf(pb[i].z));
            Bs[rb][cb + 3] = __uint_as_float(f2tf(pb[i].w));
        }
        __syncthreads();

        int kn = k0 + BK;
        if (kn < Kdim) {
#pragma unroll
            for (int i = 0; i < 4; i++) {
                int idx = i * 256 + tid;
                int c = (idx & 7) * 4;
                pa[i] = arow[i] ? *(const float4*)(arow[i] + kn + c)
                                : make_float4(0.f, 0.f, 0.f, 0.f);
                int rb = idx >> 5, cb = (idx & 31) * 4;
                pb[i] = *(const float4*)(Bmat + (size_t)(kn + rb) * Ndim + n0 + cb);
            }
        }

#pragma unroll
        for (int ks = 0; ks < 4; ks++) {
            int kk = ks * 8;
            unsigned afr[2][4];
#pragma unroll
            for (int mt = 0; mt < 2; mt++) {
                int am = warpM * 32 + mt * 16;
                afr[mt][0] = __float_as_uint(As[am + g][kk + t]);
                afr[mt][1] = __float_as_uint(As[am + g + 8][kk + t]);
                afr[mt][2] = __float_as_uint(As[am + g][kk + t + 4]);
                afr[mt][3] = __float_as_uint(As[am + g + 8][kk + t + 4]);
            }
            unsigned bfr[8][2];
#pragma unroll
            for (int nt = 0; nt < 8; nt++) {
                int bn = warpN * 64 + nt * 8;
                bfr[nt][0] = __float_as_uint(Bs[kk + t][bn + g]);
                bfr[nt][1] = __float_as_uint(Bs[kk + t + 4][bn + g]);
            }
#pragma unroll
            for (int mt = 0; mt < 2; mt++)
#pragma unroll
                for (int nt = 0; nt < 8; nt++)
                    mma_tf32(acc[mt][nt], afr[mt], bfr[nt]);
        }
        __syncthreads();
    }

    // epilogue
#pragma unroll
    for (int mt = 0; mt < 2; mt++) {
#pragma unroll
        for (int nt = 0; nt < 8; nt++) {
            int rr = m0 + warpM * 32 + mt * 16 + g;
            int col = n0 + warpN * 64 + nt * 8 + 2 * t;
#pragma unroll
            for (int half = 0; half < 2; half++) {
                int r = rr + half * 8;
                if (r < cnt) {
                    float b0 = Bias[(size_t)e * Ndim + col];
                    float b1v = Bias[(size_t)e * Ndim + col + 1];
                    float v0 = acc[mt][nt][half * 2 + 0] + b0;
                    float v1 = acc[mt][nt][half * 2 + 1] + b1v;
                    float2 o;
                    if (EP == 1) {
                        o.x = gelu_tanh(v0); o.y = gelu_tanh(v1);
                        *(float2*)(g_act + (size_t)(base + r) * FF_ + col) = o;
                    } else {
                        o.x = v0; o.y = v1;
                        *(float2*)(g_y + (size_t)(base + r) * D_ + col) = o;
                    }
                }
            }
        }
    }
}

// ---------------- launch ----------------
extern "C" void kernel_launch(void* const* d_in, const int* in_sizes, int n_in,
                              void* d_out, int out_size) {
    const float* x     = (const float*)d_in[0];
    const float* anw   = (const float*)d_in[1];
    const float* wq    = (const float*)d_in[2];
    const float* wk    = (const float*)d_in[3];
    const float* wv    = (const float*)d_in[4];
    const float* wo    = (const float*)d_in[5];
    const float* mnw   = (const float*)d_in[6];
    const float* rw    = (const float*)d_in[7];
    const float* w1    = (const float*)d_in[8];
    const float* b1    = (const float*)d_in[9];
    const float* w2    = (const float*)d_in[10];
    const float* b2    = (const float*)d_in[11];
    float* out = (float*)d_out;

    float *xn, *q, *k, *v, *sc, *ao, *x2, *h;
    cudaGetSymbolAddress((void**)&xn, g_xn);
    cudaGetSymbolAddress((void**)&q,  g_q);
    cudaGetSymbolAddress((void**)&k,  g_k);
    cudaGetSymbolAddress((void**)&v,  g_v);
    cudaGetSymbolAddress((void**)&sc, g_scores);
    cudaGetSymbolAddress((void**)&ao, g_attnout);
    cudaGetSymbolAddress((void**)&x2, g_x2);
    cudaGetSymbolAddress((void**)&h,  g_h);

    init_kernel<<<1, 32>>>();
    rmsnorm_kernel<<<NTOK, 256>>>(x, anw, xn);

    // QKV projections: [2048x1024] @ [1024x1024]
    dim3 gproj(8, 16, 1);
    mgemm<false, 0><<<gproj, 256>>>(xn, D_, wq, D_, q, D_, NTOK, D_, D_,
                                    0, 0, 0, 0, 0, 0, 1, nullptr, 0);
    mgemm<false, 0><<<gproj, 256>>>(xn, D_, wk, D_, k, D_, NTOK, D_, D_,
                                    0, 0, 0, 0, 0, 0, 1, nullptr, 0);
    mgemm<false, 0><<<gproj, 256>>>(xn, D_, wv, D_, v, D_, NTOK, D_, D_,
                                    0, 0, 0, 0, 0, 0, 1, nullptr, 0);

    // scores = Q @ K^T per (b,h), causal tile skip
    {
        dim3 g(8, 8, BB_ * NH_);
        long long sSD = (long long)S_ * D_;
        long long sSS = (long long)S_ * S_;
        mgemm<true, 0><<<g, 256>>>(q, D_, k, D_, sc, S_, S_, S_, DH_,
                                   sSD, DH_, sSD, DH_, NH_ * sSS, sSS, NH_,
                                   nullptr, 1);
    }

    softmax_kernel<<<BB_ * NH_ * S_, 128>>>(sc);

    // attnout = P @ V per (b,h), k-clipped
    {
        dim3 g(1, 8, BB_ * NH_);
        long long sSD = (long long)S_ * D_;
        long long sSS = (long long)S_ * S_;
        mgemm<false, 0><<<g, 256>>>(sc, S_, v, D_, ao, D_, S_, DH_, S_,
                                    NH_ * sSS, sSS, sSD, DH_, sSD, DH_, NH_,
                                    nullptr, 2);
    }

    // x2 = x + attnout @ wo
    mgemm<false, 1><<<gproj, 256>>>(ao, D_, wo, D_, x2, D_, NTOK, D_, D_,
                                    0, 0, 0, 0, 0, 0, 1, x, 0);

    rmsnorm_kernel<<<NTOK, 256>>>(x2, mnw, h);
    router_kernel<<<NTOK, 256>>>(h, rw);
    scan_kernel<<<1, 1>>>();
    place_kernel<<<(NTOK + 255) / 256, 256>>>();

    // expert GEMMs (grouped, early-exit on count)
    moe_mgemm<1><<<dim3(FF_ / 128, NSLOT / 128, E_), 256>>>(h, w1, b1, D_, FF_);
    moe_mgemm<2><<<dim3(D_ / 128, NSLOT / 128, E_), 256>>>(nullptr, w2, b2, FF_, D_);

    combine_kernel<<<(NTOK * D_ + 255) / 256, 256>>>(out);
    finalize_kernel<<<1, 32>>>(out);
}